// round 3
// baseline (speedup 1.0000x reference)
#include <cuda_runtime.h>
#include <cuda_bf16.h>

#define NN 100000
#define EE 1600000
#define DIN 24
#define DH 64
#define DOUT 12
#define NEG_SLOPE 0.01f

typedef unsigned long long ull;

// packed fp32x2 FMA (FFMA2) — PTX-only on sm_103a
#define FMA2(d, a, b) asm("fma.rn.f32x2 %0, %1, %2, %0;" : "+l"(d) : "l"(a), "l"(b))
#define UNPK(lo, hi, v) asm("mov.b64 {%0,%1}, %2;" : "=f"(lo), "=f"(hi) : "l"(v))

// ---------------- scratch (static device globals; allocation-free) -----------
__device__ __align__(16) float g_h[NN * DH];     // current node features (updated in place)
__device__ __align__(16) float g_hs[NN * DH];    // h @ W_self.T
__device__ __align__(16) float g_z[NN * DH];     // h @ W_func.T
__device__ float g_ssrc[NN];
__device__ float g_sdst[NN];
__device__ int   g_rowstart[NN + 1];
__device__ int   g_cursor[NN];                   // histogram counts / scatter cursor
__device__ __align__(16) int2 g_edge[EE];        // (src, bitcast(e_w)) sorted by dst
__device__ int   g_blocksums[128];
__device__ float g_c[4];                         // {c1_l1, c0_l1, c1_l2, c0_l2}

// ---------------- tiny: per-layer edge scalar coefficients -------------------
__global__ void k_coeffs(const float* __restrict__ eW, const float* __restrict__ eb,
                         const float* __restrict__ a1, const float* __restrict__ a2) {
    __shared__ float sh[4][64];
    int j = threadIdx.x;
    sh[0][j] = eW[j] * a1[128 + j];
    sh[1][j] = eb[j] * a1[128 + j];
    sh[2][j] = eW[j] * a2[128 + j];
    sh[3][j] = eb[j] * a2[128 + j];
    __syncthreads();
    if (j < 4) {
        float s = 0.f;
        #pragma unroll
        for (int k = 0; k < 64; k++) s += sh[j][k];
        g_c[j] = s;
    }
}

// ---------------- input embedding: h = feats @ emb_h_W.T + b -----------------
__global__ void k_embed(const float* __restrict__ feats, const float* __restrict__ W,
                        const float* __restrict__ b) {
    __shared__ float w_sm[64 * 25];
    __shared__ float f_sm[4 * 25];
    __shared__ float b_sm[64];
    int t = threadIdx.x;
    int node0 = blockIdx.x * 4;
    for (int idx = t; idx < 64 * 24; idx += 256)
        w_sm[(idx / 24) * 25 + (idx % 24)] = W[idx];
    for (int idx = t; idx < 4 * 24; idx += 256)
        f_sm[(idx / 24) * 25 + (idx % 24)] = feats[(node0 + idx / 24) * 24 + (idx % 24)];
    if (t < 64) b_sm[t] = b[t];
    __syncthreads();
    int ch = t & 63, nl = t >> 6;
    float acc = b_sm[ch];
    #pragma unroll
    for (int k = 0; k < 24; k++)
        acc += f_sm[nl * 25 + k] * w_sm[ch * 25 + k];
    g_h[(node0 + nl) * 64 + ch] = acc;
}

// ---------------- CSR build --------------------------------------------------
__global__ void k_hist(const int* __restrict__ dst) {
    int e = blockIdx.x * 256 + threadIdx.x;
    atomicAdd(&g_cursor[dst[e]], 1);
}

__global__ void k_scan1() {
    __shared__ int sh[256];
    int t = threadIdx.x;
    int base = blockIdx.x * 1024 + t * 4;
    int v[4];
    #pragma unroll
    for (int i = 0; i < 4; i++) v[i] = (base + i < NN) ? g_cursor[base + i] : 0;
    int s = v[0] + v[1] + v[2] + v[3];
    sh[t] = s;
    __syncthreads();
    for (int off = 1; off < 256; off <<= 1) {
        int x = 0;
        if (t >= off) x = sh[t - off];
        __syncthreads();
        if (t >= off) sh[t] += x;
        __syncthreads();
    }
    int run = sh[t] - s;  // exclusive
    #pragma unroll
    for (int i = 0; i < 4; i++) {
        if (base + i < NN) g_rowstart[base + i] = run;
        run += v[i];
    }
    if (t == 255) g_blocksums[blockIdx.x] = sh[255];
}

__global__ void k_scan2(int nb) {
    if (threadIdx.x == 0) {
        int run = 0;
        for (int i = 0; i < nb; i++) { int x = g_blocksums[i]; g_blocksums[i] = run; run += x; }
    }
}

__global__ void k_scan3() {
    int t = threadIdx.x;
    int base = blockIdx.x * 1024 + t * 4;
    int add = g_blocksums[blockIdx.x];
    #pragma unroll
    for (int i = 0; i < 4; i++)
        if (base + i < NN) g_rowstart[base + i] += add;
    if (blockIdx.x == 0 && t == 0) g_rowstart[NN] = EE;
}

__global__ void k_scatter(const int* __restrict__ src, const int* __restrict__ dst,
                          const float* __restrict__ ew) {
    int e = blockIdx.x * 256 + threadIdx.x;
    int d = dst[e];
    int p = g_rowstart[d] + atomicAdd(&g_cursor[d], 1);
    g_edge[p] = make_int2(src[e], __float_as_int(ew[e]));
}

// ---------------- node transform (FFMA2) + fused attention scores ------------
// hs = h@Ws.T, z = h@Wf.T, s_src = z@a_src, s_dst = z@a_dst
// Thread owns one output channel row of W (32 packed f32x2 regs), h tile
// broadcast from smem via LDS.64, 8 node-accumulator pairs per thread.
__global__ __launch_bounds__(256) void k_xform(const float* __restrict__ Wself,
                                               const float* __restrict__ Wfunc,
                                               const float* __restrict__ attn) {
    __shared__ float2 h_sm[16][32];          // 16 nodes x 64 floats
    __shared__ float s_ps[2][2][8];          // [half][ch-half][node]
    __shared__ float s_pd[2][2][8];
    int t = threadIdx.x;
    int ch = t & 63;
    int sel = t >> 6;            // 0..3
    int mat = sel >> 1;          // 0 = self, 1 = func
    int half = sel & 1;          // node half
    int node0 = blockIdx.x * 16;

    {   // load 16 x 64 h tile (256 float4, one per thread)
        int nn = t >> 4, kk = t & 15;
        ((float4*)&h_sm[nn][0])[kk] = ((const float4*)g_h)[(node0 + nn) * 16 + kk];
    }
    __syncthreads();

    const ull* W2 = (const ull*)((mat ? Wfunc : Wself) + ch * 64);
    ull w2[32];
    #pragma unroll
    for (int i = 0; i < 32; i++) w2[i] = W2[i];

    ull accA[8], accB[8];
    #pragma unroll
    for (int n = 0; n < 8; n++) { accA[n] = 0ull; accB[n] = 0ull; }

    #pragma unroll
    for (int k = 0; k < 16; k++) {
        ull wlo = w2[2 * k], whi = w2[2 * k + 1];
        #pragma unroll
        for (int n = 0; n < 8; n++) {
            ull hlo = *(const ull*)&h_sm[half * 8 + n][2 * k];
            ull hhi = *(const ull*)&h_sm[half * 8 + n][2 * k + 1];
            FMA2(accA[n], wlo, hlo);
            FMA2(accB[n], whi, hhi);
        }
    }

    float acc[8];
    #pragma unroll
    for (int n = 0; n < 8; n++) {
        float ax, ay, bx, by;
        UNPK(ax, ay, accA[n]);
        UNPK(bx, by, accB[n]);
        acc[n] = (ax + bx) + (ay + by);
    }

    float* out = mat ? g_z : g_hs;
    #pragma unroll
    for (int n = 0; n < 8; n++)
        out[(node0 + half * 8 + n) * 64 + ch] = acc[n];

    // fused scores: only the z-producing threads (mat==1) reduce acc over ch
    if (mat) {
        float as = attn[ch];
        float ad = attn[64 + ch];
        int wh = ch >> 5;  // which 32-ch half this warp covers
        #pragma unroll
        for (int n = 0; n < 8; n++) {
            float ps = acc[n] * as;
            float pd = acc[n] * ad;
            #pragma unroll
            for (int o = 16; o > 0; o >>= 1) {
                ps += __shfl_xor_sync(0xffffffffu, ps, o);
                pd += __shfl_xor_sync(0xffffffffu, pd, o);
            }
            if ((t & 31) == 0) { s_ps[half][wh][n] = ps; s_pd[half][wh][n] = pd; }
        }
    }
    __syncthreads();
    if (t < 16) {
        int hh = t >> 3, n = t & 7;
        int node = node0 + hh * 8 + n;
        g_ssrc[node] = s_ps[hh][0][n] + s_ps[hh][1][n];
        g_sdst[node] = s_pd[hh][0][n] + s_pd[hh][1][n];
    }
}

// ---------------- edge aggregation + node epilogue (warp per node) -----------
// 4-wide software pipeline: 12 independent loads in flight per iteration.
__global__ __launch_bounds__(256) void k_agg(int layer) {
    int n = blockIdx.x * 8 + (threadIdx.x >> 5);
    int lane = threadIdx.x & 31;
    float c1 = g_c[layer * 2 + 0];
    float c0 = g_c[layer * 2 + 1];
    int beg = g_rowstart[n];
    int end = g_rowstart[n + 1];
    float base = g_sdst[n] + c0;

    float a0 = 0.f, a1 = 0.f, den = 0.f;
    int i = beg;

    for (; i + 4 <= end; i += 4) {
        int2 e0 = g_edge[i + 0];
        int2 e1 = g_edge[i + 1];
        int2 e2 = g_edge[i + 2];
        int2 e3 = g_edge[i + 3];
        float t0 = g_ssrc[e0.x];
        float t1 = g_ssrc[e1.x];
        float t2 = g_ssrc[e2.x];
        float t3 = g_ssrc[e3.x];
        const float* z0 = g_z + (size_t)e0.x * 64;
        const float* z1 = g_z + (size_t)e1.x * 64;
        const float* z2 = g_z + (size_t)e2.x * 64;
        const float* z3 = g_z + (size_t)e3.x * 64;
        float z00 = z0[lane], z01 = z0[lane + 32];
        float z10 = z1[lane], z11 = z1[lane + 32];
        float z20 = z2[lane], z21 = z2[lane + 32];
        float z30 = z3[lane], z31 = z3[lane + 32];

        float v0 = t0 + base + c1 * __int_as_float(e0.y);
        float v1 = t1 + base + c1 * __int_as_float(e1.y);
        float v2 = t2 + base + c1 * __int_as_float(e2.y);
        float v3 = t3 + base + c1 * __int_as_float(e3.y);
        v0 = fmaxf(v0, NEG_SLOPE * v0);
        v1 = fmaxf(v1, NEG_SLOPE * v1);
        v2 = fmaxf(v2, NEG_SLOPE * v2);
        v3 = fmaxf(v3, NEG_SLOPE * v3);
        float x0 = __expf(v0), x1 = __expf(v1), x2 = __expf(v2), x3 = __expf(v3);

        den += (x0 + x1) + (x2 + x3);
        a0 += x0 * z00; a1 += x0 * z01;
        a0 += x1 * z10; a1 += x1 * z11;
        a0 += x2 * z20; a1 += x2 * z21;
        a0 += x3 * z30; a1 += x3 * z31;
    }
    for (; i < end; i++) {
        int2 e0 = g_edge[i];
        float e = g_ssrc[e0.x] + base + c1 * __int_as_float(e0.y);
        e = fmaxf(e, NEG_SLOPE * e);
        float ex = __expf(e);
        const float* zr = g_z + (size_t)e0.x * 64;
        den += ex;
        a0 += ex * zr[lane];
        a1 += ex * zr[lane + 32];
    }

    size_t o = (size_t)n * 64;
    float h0 = g_h[o + lane];
    float h1 = g_h[o + lane + 32];
    float r0, r1;
    if (end > beg) {
        float inv = 1.0f / den;
        r0 = g_hs[o + lane] + a0 * inv;
        r1 = g_hs[o + lane + 32] + a1 * inv;
    } else {
        r0 = h0; r1 = h1;
    }
    g_h[o + lane] = h0 + fmaxf(r0, 0.f);
    g_h[o + lane + 32] = h1 + fmaxf(r1, 0.f);
}

// ---------------- final projection: y = h @ lin1_W.T + b ---------------------
__global__ void k_final(const float* __restrict__ W, const float* __restrict__ b,
                        float* __restrict__ out) {
    int t = blockIdx.x * 256 + threadIdx.x;
    int node = t >> 4;
    int ch = t & 15;
    if (ch < 12) {
        const float4* hr = (const float4*)(g_h + (size_t)node * 64);
        const float4* wr = (const float4*)(W + ch * 64);
        float acc = b[ch];
        #pragma unroll
        for (int k = 0; k < 16; k++) {
            float4 h4 = hr[k];
            float4 w4 = wr[k];
            acc += h4.x * w4.x + h4.y * w4.y + h4.z * w4.z + h4.w * w4.w;
        }
        out[node * 12 + ch] = acc;
    }
}

// ---------------- launch -----------------------------------------------------
extern "C" void kernel_launch(void* const* d_in, const int* in_sizes, int n_in,
                              void* d_out, int out_size) {
    const float* feats   = (const float*)d_in[0];
    const float* e_w     = (const float*)d_in[1];
    const int*   src     = (const int*)d_in[4];
    const int*   dst     = (const int*)d_in[5];
    const float* emb_h_W = (const float*)d_in[6];
    const float* emb_h_b = (const float*)d_in[7];
    const float* emb_e_W = (const float*)d_in[8];
    const float* emb_e_b = (const float*)d_in[9];
    const float* W_self1 = (const float*)d_in[10];
    const float* W_func1 = (const float*)d_in[11];
    const float* attn1   = (const float*)d_in[12];
    const float* W_self2 = (const float*)d_in[13];
    const float* W_func2 = (const float*)d_in[14];
    const float* attn2   = (const float*)d_in[15];
    const float* lin1_W  = (const float*)d_in[16];
    const float* lin1_b  = (const float*)d_in[17];
    float* out = (float*)d_out;

    void* curs = nullptr;
    cudaGetSymbolAddress(&curs, g_cursor);

    const int NB_SCAN = (NN + 1023) / 1024;  // 98

    k_coeffs<<<1, 64>>>(emb_e_W, emb_e_b, attn1, attn2);
    k_embed<<<NN / 4, 256>>>(feats, emb_h_W, emb_h_b);

    // CSR build (dst-sorted edge lists)
    cudaMemsetAsync(curs, 0, NN * sizeof(int));
    k_hist<<<EE / 256, 256>>>(dst);
    k_scan1<<<NB_SCAN, 256>>>();
    k_scan2<<<1, 32>>>(NB_SCAN);
    k_scan3<<<NB_SCAN, 256>>>();
    cudaMemsetAsync(curs, 0, NN * sizeof(int));
    k_scatter<<<EE / 256, 256>>>(src, dst, e_w);

    for (int l = 0; l < 2; l++) {
        k_xform<<<NN / 16, 256>>>(l ? W_self2 : W_self1, l ? W_func2 : W_func1,
                                  l ? attn2 : attn1);
        k_agg<<<NN / 8, 256>>>(l);
    }
    k_final<<<NN * 16 / 256, 256>>>(lin1_W, lin1_b, out);
}

// round 4
// speedup vs baseline: 1.2769x; 1.2769x over previous
#include <cuda_runtime.h>
#include <cuda_bf16.h>

#define NN 100000
#define EE 1600000
#define DIN 24
#define DH 64
#define DOUT 12
#define NEG_SLOPE 0.01f

// ---------------- scratch (static device globals; allocation-free) -----------
__device__ __align__(16) float g_h[NN * DH];     // current node features (updated in place)
__device__ __align__(16) float g_hs[NN * DH];    // h @ W_self.T
__device__ __align__(16) float g_z[NN * DH];     // h @ W_func.T
__device__ float g_ssrc[NN];
__device__ float g_sdst[NN];
__device__ int   g_rowstart[NN + 1];
__device__ int   g_cursor[NN];                   // histogram counts / scatter cursor
__device__ __align__(16) int2 g_edge[EE];        // (src, bitcast(e_w)) sorted by dst
__device__ int   g_blocksums[128];
__device__ float g_c[4];                         // {c1_l1, c0_l1, c1_l2, c0_l2}

__global__ void k_nop() {}

// ---------------- tiny: per-layer edge scalar coefficients -------------------
__global__ void k_coeffs(const float* __restrict__ eW, const float* __restrict__ eb,
                         const float* __restrict__ a1, const float* __restrict__ a2) {
    __shared__ float sh[4][64];
    int j = threadIdx.x;
    sh[0][j] = eW[j] * a1[128 + j];
    sh[1][j] = eb[j] * a1[128 + j];
    sh[2][j] = eW[j] * a2[128 + j];
    sh[3][j] = eb[j] * a2[128 + j];
    __syncthreads();
    if (j < 4) {
        float s = 0.f;
        #pragma unroll
        for (int k = 0; k < 64; k++) s += sh[j][k];
        g_c[j] = s;
    }
}

// ---------------- input embedding: h = feats @ emb_h_W.T + b -----------------
__global__ void k_embed(const float* __restrict__ feats, const float* __restrict__ W,
                        const float* __restrict__ b) {
    __shared__ float w_sm[64 * 25];
    __shared__ float f_sm[4 * 25];
    __shared__ float b_sm[64];
    int t = threadIdx.x;
    int node0 = blockIdx.x * 4;
    for (int idx = t; idx < 64 * 24; idx += 256)
        w_sm[(idx / 24) * 25 + (idx % 24)] = W[idx];
    for (int idx = t; idx < 4 * 24; idx += 256)
        f_sm[(idx / 24) * 25 + (idx % 24)] = feats[(node0 + idx / 24) * 24 + (idx % 24)];
    if (t < 64) b_sm[t] = b[t];
    __syncthreads();
    int ch = t & 63, nl = t >> 6;
    float acc = b_sm[ch];
    #pragma unroll
    for (int k = 0; k < 24; k++)
        acc += f_sm[nl * 25 + k] * w_sm[ch * 25 + k];
    g_h[(node0 + nl) * 64 + ch] = acc;
}

// ---------------- CSR build --------------------------------------------------
__global__ void k_hist(const int* __restrict__ dst) {
    int e = blockIdx.x * 256 + threadIdx.x;
    atomicAdd(&g_cursor[dst[e]], 1);
}

__global__ void k_scan1() {
    __shared__ int sh[256];
    int t = threadIdx.x;
    int base = blockIdx.x * 1024 + t * 4;
    int v[4];
    #pragma unroll
    for (int i = 0; i < 4; i++) v[i] = (base + i < NN) ? g_cursor[base + i] : 0;
    int s = v[0] + v[1] + v[2] + v[3];
    sh[t] = s;
    __syncthreads();
    for (int off = 1; off < 256; off <<= 1) {
        int x = 0;
        if (t >= off) x = sh[t - off];
        __syncthreads();
        if (t >= off) sh[t] += x;
        __syncthreads();
    }
    int run = sh[t] - s;  // exclusive
    #pragma unroll
    for (int i = 0; i < 4; i++) {
        if (base + i < NN) g_rowstart[base + i] = run;
        run += v[i];
    }
    if (t == 255) g_blocksums[blockIdx.x] = sh[255];
}

__global__ void k_scan2(int nb) {
    if (threadIdx.x == 0) {
        int run = 0;
        for (int i = 0; i < nb; i++) { int x = g_blocksums[i]; g_blocksums[i] = run; run += x; }
    }
}

__global__ void k_scan3() {
    int t = threadIdx.x;
    int base = blockIdx.x * 1024 + t * 4;
    int add = g_blocksums[blockIdx.x];
    #pragma unroll
    for (int i = 0; i < 4; i++)
        if (base + i < NN) g_rowstart[base + i] += add;
    if (blockIdx.x == 0 && t == 0) g_rowstart[NN] = EE;
}

__global__ void k_scatter(const int* __restrict__ src, const int* __restrict__ dst,
                          const float* __restrict__ ew) {
    int e = blockIdx.x * 256 + threadIdx.x;
    int d = dst[e];
    int p = g_rowstart[d] + atomicAdd(&g_cursor[d], 1);
    g_edge[p] = make_int2(src[e], __float_as_int(ew[e]));
}

// ---------------- node transform: hs = h@Ws.T, z = h@Wf.T --------------------
// Weight-stationary: thread owns one output channel row of W (64 regs),
// h tile broadcast from smem, 8 node-accumulators per thread. (R1 form.)
__global__ __launch_bounds__(256) void k_xform(const float* __restrict__ Wself,
                                               const float* __restrict__ Wfunc) {
    __shared__ float4 h_sm[16][16];
    int t = threadIdx.x;
    int ch = t & 63;
    int sel = t >> 6;            // 0..3
    int mat = sel >> 1;          // 0 = self, 1 = func
    int half = sel & 1;          // node half
    int node0 = blockIdx.x * 16;

    {   // load 16 x 64 h tile (256 float4, one per thread)
        int nn = t >> 4, kk = t & 15;
        h_sm[nn][kk] = ((const float4*)g_h)[(node0 + nn) * 16 + kk];
    }
    __syncthreads();

    const float4* W4 = (const float4*)((mat ? Wfunc : Wself) + ch * 64);
    float4 w4[16];
    #pragma unroll
    for (int i = 0; i < 16; i++) w4[i] = W4[i];

    float acc[8];
    #pragma unroll
    for (int n = 0; n < 8; n++) acc[n] = 0.f;

    #pragma unroll
    for (int k = 0; k < 16; k++) {
        float4 wv = w4[k];
        #pragma unroll
        for (int n = 0; n < 8; n++) {
            float4 hv = h_sm[half * 8 + n][k];
            acc[n] += wv.x * hv.x;
            acc[n] += wv.y * hv.y;
            acc[n] += wv.z * hv.z;
            acc[n] += wv.w * hv.w;
        }
    }
    float* out = mat ? g_z : g_hs;
    #pragma unroll
    for (int n = 0; n < 8; n++)
        out[(node0 + half * 8 + n) * 64 + ch] = acc[n];
}

// ---------------- attention scores: s_src = z@a_src, s_dst = z@a_dst ---------
__global__ void k_scores(const float* __restrict__ attn) {
    int n = blockIdx.x * 8 + (threadIdx.x >> 5);
    int lane = threadIdx.x & 31;
    float z0 = g_z[n * 64 + lane];
    float z1 = g_z[n * 64 + 32 + lane];
    float ps = z0 * attn[lane] + z1 * attn[32 + lane];
    float pd = z0 * attn[64 + lane] + z1 * attn[96 + lane];
    #pragma unroll
    for (int o = 16; o > 0; o >>= 1) {
        ps += __shfl_xor_sync(0xffffffffu, ps, o);
        pd += __shfl_xor_sync(0xffffffffu, pd, o);
    }
    if (lane == 0) { g_ssrc[n] = ps; g_sdst[n] = pd; }
}

// ---------------- edge aggregation + node epilogue (warp per node) -----------
// 4-wide batched loads: 12 independent loads in flight per iteration.
__global__ __launch_bounds__(256) void k_agg(int layer) {
    int n = blockIdx.x * 8 + (threadIdx.x >> 5);
    int lane = threadIdx.x & 31;
    float c1 = g_c[layer * 2 + 0];
    float c0 = g_c[layer * 2 + 1];
    int beg = g_rowstart[n];
    int end = g_rowstart[n + 1];
    float base = g_sdst[n] + c0;

    float a0 = 0.f, a1 = 0.f, den = 0.f;
    int i = beg;

    for (; i + 4 <= end; i += 4) {
        int2 e0 = g_edge[i + 0];
        int2 e1 = g_edge[i + 1];
        int2 e2 = g_edge[i + 2];
        int2 e3 = g_edge[i + 3];
        float t0 = g_ssrc[e0.x];
        float t1 = g_ssrc[e1.x];
        float t2 = g_ssrc[e2.x];
        float t3 = g_ssrc[e3.x];
        const float* z0 = g_z + (size_t)e0.x * 64;
        const float* z1 = g_z + (size_t)e1.x * 64;
        const float* z2 = g_z + (size_t)e2.x * 64;
        const float* z3 = g_z + (size_t)e3.x * 64;
        float z00 = z0[lane], z01 = z0[lane + 32];
        float z10 = z1[lane], z11 = z1[lane + 32];
        float z20 = z2[lane], z21 = z2[lane + 32];
        float z30 = z3[lane], z31 = z3[lane + 32];

        float v0 = t0 + base + c1 * __int_as_float(e0.y);
        float v1 = t1 + base + c1 * __int_as_float(e1.y);
        float v2 = t2 + base + c1 * __int_as_float(e2.y);
        float v3 = t3 + base + c1 * __int_as_float(e3.y);
        v0 = fmaxf(v0, NEG_SLOPE * v0);
        v1 = fmaxf(v1, NEG_SLOPE * v1);
        v2 = fmaxf(v2, NEG_SLOPE * v2);
        v3 = fmaxf(v3, NEG_SLOPE * v3);
        float x0 = __expf(v0), x1 = __expf(v1), x2 = __expf(v2), x3 = __expf(v3);

        den += (x0 + x1) + (x2 + x3);
        a0 += x0 * z00; a1 += x0 * z01;
        a0 += x1 * z10; a1 += x1 * z11;
        a0 += x2 * z20; a1 += x2 * z21;
        a0 += x3 * z30; a1 += x3 * z31;
    }
    for (; i < end; i++) {
        int2 e0 = g_edge[i];
        float e = g_ssrc[e0.x] + base + c1 * __int_as_float(e0.y);
        e = fmaxf(e, NEG_SLOPE * e);
        float ex = __expf(e);
        const float* zr = g_z + (size_t)e0.x * 64;
        den += ex;
        a0 += ex * zr[lane];
        a1 += ex * zr[lane + 32];
    }

    size_t o = (size_t)n * 64;
    float h0 = g_h[o + lane];
    float h1 = g_h[o + lane + 32];
    float r0, r1;
    if (end > beg) {
        float inv = 1.0f / den;
        r0 = g_hs[o + lane] + a0 * inv;
        r1 = g_hs[o + lane + 32] + a1 * inv;
    } else {
        r0 = h0; r1 = h1;
    }
    g_h[o + lane] = h0 + fmaxf(r0, 0.f);
    g_h[o + lane + 32] = h1 + fmaxf(r1, 0.f);
}

// ---------------- final projection: y = h @ lin1_W.T + b ---------------------
__global__ void k_final(const float* __restrict__ W, const float* __restrict__ b,
                        float* __restrict__ out) {
    int t = blockIdx.x * 256 + threadIdx.x;
    int node = t >> 4;
    int ch = t & 15;
    if (ch < 12) {
        const float4* hr = (const float4*)(g_h + (size_t)node * 64);
        const float4* wr = (const float4*)(W + ch * 64);
        float acc = b[ch];
        #pragma unroll
        for (int k = 0; k < 16; k++) {
            float4 h4 = hr[k];
            float4 w4 = wr[k];
            acc += h4.x * w4.x + h4.y * w4.y + h4.z * w4.z + h4.w * w4.w;
        }
        out[node * 12 + ch] = acc;
    }
}

// ---------------- launch -----------------------------------------------------
extern "C" void kernel_launch(void* const* d_in, const int* in_sizes, int n_in,
                              void* d_out, int out_size) {
    const float* feats   = (const float*)d_in[0];
    const float* e_w     = (const float*)d_in[1];
    const int*   src     = (const int*)d_in[4];
    const int*   dst     = (const int*)d_in[5];
    const float* emb_h_W = (const float*)d_in[6];
    const float* emb_h_b = (const float*)d_in[7];
    const float* emb_e_W = (const float*)d_in[8];
    const float* emb_e_b = (const float*)d_in[9];
    const float* W_self1 = (const float*)d_in[10];
    const float* W_func1 = (const float*)d_in[11];
    const float* attn1   = (const float*)d_in[12];
    const float* W_self2 = (const float*)d_in[13];
    const float* W_func2 = (const float*)d_in[14];
    const float* attn2   = (const float*)d_in[15];
    const float* lin1_W  = (const float*)d_in[16];
    const float* lin1_b  = (const float*)d_in[17];
    float* out = (float*)d_out;

    void* curs = nullptr;
    cudaGetSymbolAddress(&curs, g_cursor);

    const int NB_SCAN = (NN + 1023) / 1024;  // 98

    // launch indices (memsetAsync observed to count as 2): align k_xform(L1) at 5
    k_coeffs<<<1, 64>>>(emb_e_W, emb_e_b, attn1, attn2);     // 0
    k_embed<<<NN / 4, 256>>>(feats, emb_h_W, emb_h_b);       // 1
    k_nop<<<1, 32>>>();                                      // 2
    k_nop<<<1, 32>>>();                                      // 3
    k_nop<<<1, 32>>>();                                      // 4
    k_xform<<<NN / 16, 256>>>(W_self1, W_func1);             // 5  <- ncu target

    // CSR build (dst-sorted edge lists)
    cudaMemsetAsync(curs, 0, NN * sizeof(int));
    k_hist<<<EE / 256, 256>>>(dst);
    k_scan1<<<NB_SCAN, 256>>>();
    k_scan2<<<1, 32>>>(NB_SCAN);
    k_scan3<<<NB_SCAN, 256>>>();
    cudaMemsetAsync(curs, 0, NN * sizeof(int));
    k_scatter<<<EE / 256, 256>>>(src, dst, e_w);

    // layer 1 (xform already launched above)
    k_scores<<<NN / 8, 256>>>(attn1);
    k_agg<<<NN / 8, 256>>>(0);
    // layer 2
    k_xform<<<NN / 16, 256>>>(W_self2, W_func2);
    k_scores<<<NN / 8, 256>>>(attn2);
    k_agg<<<NN / 8, 256>>>(1);

    k_final<<<NN * 16 / 256, 256>>>(lin1_W, lin1_b, out);
}

// round 5
// speedup vs baseline: 1.4081x; 1.1028x over previous
#include <cuda_runtime.h>
#include <cuda_bf16.h>

#define NN 100000
#define EE 1600000
#define DIN 24
#define DH 64
#define DOUT 12
#define NEG_SLOPE 0.01f

// ---------------- scratch (static device globals; allocation-free) -----------
__device__ __align__(16) float g_h[NN * DH];     // current node features
__device__ __align__(16) float g_hs[NN * DH];    // h @ W_self.T
__device__ __align__(16) float g_z[NN * DH];     // h @ W_func.T
__device__ float g_ssrc[NN];
__device__ float g_sdst[NN];
__device__ int   g_rowstart[NN + 1];
__device__ int   g_cursor[NN];                   // histogram counts / scatter cursor
__device__ __align__(16) int2 g_edge[EE];        // (src, bitcast(e_w)) sorted by dst
__device__ int   g_blocksums[128];
__device__ float g_c[4];                         // {c1_l1, c0_l1, c1_l2, c0_l2}

__global__ void k_nop() {}

// ---------------- tiny: per-layer edge scalar coefficients -------------------
__global__ void k_coeffs(const float* __restrict__ eW, const float* __restrict__ eb,
                         const float* __restrict__ a1, const float* __restrict__ a2) {
    __shared__ float sh[4][64];
    int j = threadIdx.x;
    sh[0][j] = eW[j] * a1[128 + j];
    sh[1][j] = eb[j] * a1[128 + j];
    sh[2][j] = eW[j] * a2[128 + j];
    sh[3][j] = eb[j] * a2[128 + j];
    __syncthreads();
    if (j < 4) {
        float s = 0.f;
        #pragma unroll
        for (int k = 0; k < 64; k++) s += sh[j][k];
        g_c[j] = s;
    }
}

// ---------------- input embedding: h = feats @ emb_h_W.T + b -----------------
__global__ void k_embed(const float* __restrict__ feats, const float* __restrict__ W,
                        const float* __restrict__ b) {
    __shared__ float w_sm[64 * 25];
    __shared__ float f_sm[4 * 25];
    __shared__ float b_sm[64];
    int t = threadIdx.x;
    int node0 = blockIdx.x * 4;
    for (int idx = t; idx < 64 * 24; idx += 256)
        w_sm[(idx / 24) * 25 + (idx % 24)] = W[idx];
    for (int idx = t; idx < 4 * 24; idx += 256)
        f_sm[(idx / 24) * 25 + (idx % 24)] = feats[(node0 + idx / 24) * 24 + (idx % 24)];
    if (t < 64) b_sm[t] = b[t];
    __syncthreads();
    int ch = t & 63, nl = t >> 6;
    float acc = b_sm[ch];
    #pragma unroll
    for (int k = 0; k < 24; k++)
        acc += f_sm[nl * 25 + k] * w_sm[ch * 25 + k];
    g_h[(node0 + nl) * 64 + ch] = acc;
}

// ---------------- CSR build --------------------------------------------------
__global__ void k_hist(const int* __restrict__ dst) {
    int e = blockIdx.x * 256 + threadIdx.x;
    atomicAdd(&g_cursor[dst[e]], 1);
}

// scan of counts -> rowstart (per-block); also zeroes cursor for the scatter pass
__global__ void k_scan1() {
    __shared__ int sh[256];
    int t = threadIdx.x;
    int base = blockIdx.x * 1024 + t * 4;
    int v[4];
    #pragma unroll
    for (int i = 0; i < 4; i++) v[i] = (base + i < NN) ? g_cursor[base + i] : 0;
    #pragma unroll
    for (int i = 0; i < 4; i++) if (base + i < NN) g_cursor[base + i] = 0;
    int s = v[0] + v[1] + v[2] + v[3];
    sh[t] = s;
    __syncthreads();
    for (int off = 1; off < 256; off <<= 1) {
        int x = 0;
        if (t >= off) x = sh[t - off];
        __syncthreads();
        if (t >= off) sh[t] += x;
        __syncthreads();
    }
    int run = sh[t] - s;  // exclusive
    #pragma unroll
    for (int i = 0; i < 4; i++) {
        if (base + i < NN) g_rowstart[base + i] = run;
        run += v[i];
    }
    if (t == 255) g_blocksums[blockIdx.x] = sh[255];
}

// adds inter-block prefix (reduction of blocksums done per-block; replaces scan2)
__global__ void k_scan3() {
    __shared__ int sred[256];
    int t = threadIdx.x;
    int v = 0;
    if (t < (int)blockIdx.x && t < 128) v = g_blocksums[t];
    sred[t] = v;
    __syncthreads();
    #pragma unroll
    for (int s = 128; s > 0; s >>= 1) {
        if (t < s) sred[t] += sred[t + s];
        __syncthreads();
    }
    int add = sred[0];
    int base = blockIdx.x * 1024 + t * 4;
    #pragma unroll
    for (int i = 0; i < 4; i++)
        if (base + i < NN) g_rowstart[base + i] += add;
    if (blockIdx.x == 0 && t == 0) g_rowstart[NN] = EE;
}

__global__ void k_scatter(const int* __restrict__ src, const int* __restrict__ dst,
                          const float* __restrict__ ew) {
    int e = blockIdx.x * 256 + threadIdx.x;
    int d = dst[e];
    int p = g_rowstart[d] + atomicAdd(&g_cursor[d], 1);
    g_edge[p] = make_int2(src[e], __float_as_int(ew[e]));
}

// ---------------- node transform: hs = h@Ws.T, z = h@Wf.T --------------------
__global__ __launch_bounds__(256) void k_xform(const float* __restrict__ Wself,
                                               const float* __restrict__ Wfunc) {
    __shared__ float4 h_sm[16][16];
    int t = threadIdx.x;
    int ch = t & 63;
    int sel = t >> 6;            // 0..3
    int mat = sel >> 1;          // 0 = self, 1 = func
    int half = sel & 1;          // node half
    int node0 = blockIdx.x * 16;

    {   // load 16 x 64 h tile (256 float4, one per thread)
        int nn = t >> 4, kk = t & 15;
        h_sm[nn][kk] = ((const float4*)g_h)[(node0 + nn) * 16 + kk];
    }
    __syncthreads();

    const float4* W4 = (const float4*)((mat ? Wfunc : Wself) + ch * 64);
    float4 w4[16];
    #pragma unroll
    for (int i = 0; i < 16; i++) w4[i] = W4[i];

    float acc[8];
    #pragma unroll
    for (int n = 0; n < 8; n++) acc[n] = 0.f;

    #pragma unroll
    for (int k = 0; k < 16; k++) {
        float4 wv = w4[k];
        #pragma unroll
        for (int n = 0; n < 8; n++) {
            float4 hv = h_sm[half * 8 + n][k];
            acc[n] += wv.x * hv.x;
            acc[n] += wv.y * hv.y;
            acc[n] += wv.z * hv.z;
            acc[n] += wv.w * hv.w;
        }
    }
    float* out = mat ? g_z : g_hs;
    #pragma unroll
    for (int n = 0; n < 8; n++)
        out[(node0 + half * 8 + n) * 64 + ch] = acc[n];
}

// ---------------- attention scores: s_src = z@a_src, s_dst = z@a_dst ---------
__global__ void k_scores(const float* __restrict__ attn) {
    int n = blockIdx.x * 8 + (threadIdx.x >> 5);
    int lane = threadIdx.x & 31;
    float z0 = g_z[n * 64 + lane];
    float z1 = g_z[n * 64 + 32 + lane];
    float ps = z0 * attn[lane] + z1 * attn[32 + lane];
    float pd = z0 * attn[64 + lane] + z1 * attn[96 + lane];
    #pragma unroll
    for (int o = 16; o > 0; o >>= 1) {
        ps += __shfl_xor_sync(0xffffffffu, ps, o);
        pd += __shfl_xor_sync(0xffffffffu, pd, o);
    }
    if (lane == 0) { g_ssrc[n] = ps; g_sdst[n] = pd; }
}

// ---------------- edge aggregation + node epilogue (warp per node) -----------
// layer 0: writes updated h. layer 1: fused final projection, writes y only.
__global__ __launch_bounds__(256) void k_agg(int layer, const float* __restrict__ linW,
                                             const float* __restrict__ linb,
                                             float* __restrict__ out) {
    __shared__ float w_sm[12][64];
    __shared__ float b_sm[12];
    int t = threadIdx.x;
    if (layer) {
        for (int idx = t; idx < 12 * 64; idx += 256)
            w_sm[idx >> 6][idx & 63] = linW[idx];
        if (t < 12) b_sm[t] = linb[t];
    }
    __syncthreads();

    int n = blockIdx.x * 8 + (t >> 5);
    int lane = t & 31;
    float c1 = g_c[layer * 2 + 0];
    float c0 = g_c[layer * 2 + 1];
    int beg = g_rowstart[n];
    int end = g_rowstart[n + 1];
    float base = g_sdst[n] + c0;

    float a0 = 0.f, a1 = 0.f, den = 0.f;
    int i = beg;

    for (; i + 4 <= end; i += 4) {
        int2 e0 = g_edge[i + 0];
        int2 e1 = g_edge[i + 1];
        int2 e2 = g_edge[i + 2];
        int2 e3 = g_edge[i + 3];
        float t0 = g_ssrc[e0.x];
        float t1 = g_ssrc[e1.x];
        float t2 = g_ssrc[e2.x];
        float t3 = g_ssrc[e3.x];
        const float* z0 = g_z + (size_t)e0.x * 64;
        const float* z1 = g_z + (size_t)e1.x * 64;
        const float* z2 = g_z + (size_t)e2.x * 64;
        const float* z3 = g_z + (size_t)e3.x * 64;
        float z00 = z0[lane], z01 = z0[lane + 32];
        float z10 = z1[lane], z11 = z1[lane + 32];
        float z20 = z2[lane], z21 = z2[lane + 32];
        float z30 = z3[lane], z31 = z3[lane + 32];

        float v0 = t0 + base + c1 * __int_as_float(e0.y);
        float v1 = t1 + base + c1 * __int_as_float(e1.y);
        float v2 = t2 + base + c1 * __int_as_float(e2.y);
        float v3 = t3 + base + c1 * __int_as_float(e3.y);
        v0 = fmaxf(v0, NEG_SLOPE * v0);
        v1 = fmaxf(v1, NEG_SLOPE * v1);
        v2 = fmaxf(v2, NEG_SLOPE * v2);
        v3 = fmaxf(v3, NEG_SLOPE * v3);
        float x0 = __expf(v0), x1 = __expf(v1), x2 = __expf(v2), x3 = __expf(v3);

        den += (x0 + x1) + (x2 + x3);
        a0 += x0 * z00; a1 += x0 * z01;
        a0 += x1 * z10; a1 += x1 * z11;
        a0 += x2 * z20; a1 += x2 * z21;
        a0 += x3 * z30; a1 += x3 * z31;
    }
    for (; i < end; i++) {
        int2 e0 = g_edge[i];
        float e = g_ssrc[e0.x] + base + c1 * __int_as_float(e0.y);
        e = fmaxf(e, NEG_SLOPE * e);
        float ex = __expf(e);
        const float* zr = g_z + (size_t)e0.x * 64;
        den += ex;
        a0 += ex * zr[lane];
        a1 += ex * zr[lane + 32];
    }

    size_t o = (size_t)n * 64;
    float h0 = g_h[o + lane];
    float h1 = g_h[o + lane + 32];
    float r0, r1;
    if (end > beg) {
        float inv = 1.0f / den;
        r0 = g_hs[o + lane] + a0 * inv;
        r1 = g_hs[o + lane + 32] + a1 * inv;
    } else {
        r0 = h0; r1 = h1;
    }
    float hn0 = h0 + fmaxf(r0, 0.f);
    float hn1 = h1 + fmaxf(r1, 0.f);

    if (!layer) {
        g_h[o + lane] = hn0;
        g_h[o + lane + 32] = hn1;
    } else {
        // fused final projection: y[n] = h_new @ linW.T + b
        float yv = 0.f;
        #pragma unroll
        for (int c = 0; c < 12; c++) {
            float p = hn0 * w_sm[c][lane] + hn1 * w_sm[c][lane + 32];
            #pragma unroll
            for (int off = 16; off > 0; off >>= 1)
                p += __shfl_xor_sync(0xffffffffu, p, off);
            if (lane == c) yv = p + b_sm[c];
        }
        if (lane < 12) out[n * 12 + lane] = yv;
    }
}

// ---------------- launch -----------------------------------------------------
extern "C" void kernel_launch(void* const* d_in, const int* in_sizes, int n_in,
                              void* d_out, int out_size) {
    const float* feats   = (const float*)d_in[0];
    const float* e_w     = (const float*)d_in[1];
    const int*   src     = (const int*)d_in[4];
    const int*   dst     = (const int*)d_in[5];
    const float* emb_h_W = (const float*)d_in[6];
    const float* emb_h_b = (const float*)d_in[7];
    const float* emb_e_W = (const float*)d_in[8];
    const float* emb_e_b = (const float*)d_in[9];
    const float* W_self1 = (const float*)d_in[10];
    const float* W_func1 = (const float*)d_in[11];
    const float* attn1   = (const float*)d_in[12];
    const float* W_self2 = (const float*)d_in[13];
    const float* W_func2 = (const float*)d_in[14];
    const float* attn2   = (const float*)d_in[15];
    const float* lin1_W  = (const float*)d_in[16];
    const float* lin1_b  = (const float*)d_in[17];
    float* out = (float*)d_out;

    void* curs = nullptr;
    cudaGetSymbolAddress(&curs, g_cursor);

    const int NB_SCAN = (NN + 1023) / 1024;  // 98

    // ncu captures 0-based launch index 4 -> k_xform (L1)
    k_coeffs<<<1, 64>>>(emb_e_W, emb_e_b, attn1, attn2);     // 0
    k_embed<<<NN / 4, 256>>>(feats, emb_h_W, emb_h_b);       // 1
    k_nop<<<1, 32>>>();                                      // 2
    k_nop<<<1, 32>>>();                                      // 3
    k_xform<<<NN / 16, 256>>>(W_self1, W_func1);             // 4  <- ncu target

    // CSR build (dst-sorted edge lists)
    cudaMemsetAsync(curs, 0, NN * sizeof(int));              // 5
    k_hist<<<EE / 256, 256>>>(dst);                          // 6
    k_scan1<<<NB_SCAN, 256>>>();                             // 7 (also zeroes cursor)
    k_scan3<<<NB_SCAN, 256>>>();                             // 8 (includes blocksum prefix)
    k_scatter<<<EE / 256, 256>>>(src, dst, e_w);             // 9

    // layer 1 (xform already launched above)
    k_scores<<<NN / 8, 256>>>(attn1);                        // 10
    k_agg<<<NN / 8, 256>>>(0, lin1_W, lin1_b, out);          // 11
    // layer 2 + fused final projection
    k_xform<<<NN / 16, 256>>>(W_self2, W_func2);             // 12
    k_scores<<<NN / 8, 256>>>(attn2);                        // 13
    k_agg<<<NN / 8, 256>>>(1, lin1_W, lin1_b, out);          // 14
}